// round 3
// baseline (speedup 1.0000x reference)
#include <cuda_runtime.h>

// ---------------------------------------------------------------------------
// TNModel binary-tree TN, B=65536. Round 3: half-tree split.
// Each CTA computes one half-tree (84 KB weights in smem) for 512 samples
// (2 samples/thread). 2 CTAs/SM (forced via launch_bounds 128 regs) ->
// 16 warps/SM for latency hiding. A tiny second kernel applies the root w0.
// ---------------------------------------------------------------------------

#define NB       65536
#define THREADS  256
#define HALF     (NB / 2)               // 32768
#define NBLK_SIDE 128                   // blocks per half
#define NBLOCKS  (2 * NBLK_SIDE)        // 256

// half-tree shared-memory float offsets
#define H7 0                     // 64 x 16    = 1024
#define H6 (H7 + 1024)           // 32 x 128   = 4096
#define H5 (H6 + 4096)           // 16 x 512   = 8192
#define H4 (H5 + 8192)           //  8 x 512   = 4096
#define H3 (H4 + 4096)           //  4 x 512   = 2048
#define H2 (H3 + 2048)           //  2 x 512   = 1024
#define H1 (H2 + 1024)           //  1 x 512   =  512
#define SMEM_FLOATS (H1 + 512)   // 20992 floats = 83968 bytes

typedef unsigned long long ull;

__device__ float4 g_hbuf[2 * NB * 2];   // [side][sample][2 x float4]

__device__ __forceinline__ ull ffma2(ull a, ull b, ull c) {
    ull d;
    asm("fma.rn.f32x2 %0, %1, %2, %3;" : "=l"(d) : "l"(a), "l"(b), "l"(c));
    return d;
}
__device__ __forceinline__ ull bcast2(float x) {
    ull r;
    asm("mov.b64 %0, {%1, %1};" : "=l"(r) : "f"(x));
    return r;
}
__device__ __forceinline__ void unpack2(ull v, float& lo, float& hi) {
    asm("mov.b64 {%0, %1}, %2;" : "=f"(lo), "=f"(hi) : "l"(v));
}
__device__ __forceinline__ void cp8(float* d, const float* s) {
#pragma unroll
    for (int k = 0; k < 8; ++k) d[k] = s[k];
}

// leaf: two samples share W (16 floats). h[k<4] = sum_{i,j<2} e_i o_j w[ijk]
__device__ __forceinline__ void leaf2(float4 qa, float4 qb,
                                      const float* __restrict__ w,
                                      float* hA, float* hB) {
    ull cA0 = 0, cA1 = 0, cB0 = 0, cB1 = 0;
    float eA[2] = {qa.x, qa.y}, oA[2] = {qa.z, qa.w};
    float eB[2] = {qb.x, qb.y}, oB[2] = {qb.z, qb.w};
#pragma unroll
    for (int i = 0; i < 2; ++i) {
#pragma unroll
        for (int j = 0; j < 2; ++j) {
            const ulonglong2 W = *reinterpret_cast<const ulonglong2*>(w + (i * 2 + j) * 4);
            ull pA = bcast2(eA[i] * oA[j]);
            ull pB = bcast2(eB[i] * oB[j]);
            cA0 = ffma2(pA, W.x, cA0);  cA1 = ffma2(pA, W.y, cA1);
            cB0 = ffma2(pB, W.x, cB0);  cB1 = ffma2(pB, W.y, cB1);
        }
    }
    unpack2(cA0, hA[0], hA[1]);  unpack2(cA1, hA[2], hA[3]);
    unpack2(cB0, hB[0], hB[1]);  unpack2(cB1, hB[2], hB[3]);
}

// level-6 (4x4->8), two samples share W (128 floats)
__device__ __forceinline__ void contract448_2(const float* aA, const float* bA,
                                              const float* aB, const float* bB,
                                              const float* __restrict__ w,
                                              float* outA, float* outB) {
    ull cA[4] = {0, 0, 0, 0}, cB[4] = {0, 0, 0, 0};
    ull bbA[4], bbB[4];
#pragma unroll
    for (int j = 0; j < 4; ++j) { bbA[j] = bcast2(bA[j]); bbB[j] = bcast2(bB[j]); }
#pragma unroll
    for (int i = 0; i < 4; ++i) {
        ull tA[4] = {0, 0, 0, 0}, tB[4] = {0, 0, 0, 0};
#pragma unroll
        for (int j = 0; j < 4; ++j) {
            const ulonglong2* wp = reinterpret_cast<const ulonglong2*>(w + (i * 4 + j) * 8);
            ulonglong2 W01 = wp[0];
            ulonglong2 W23 = wp[1];
            tA[0] = ffma2(bbA[j], W01.x, tA[0]);  tA[1] = ffma2(bbA[j], W01.y, tA[1]);
            tA[2] = ffma2(bbA[j], W23.x, tA[2]);  tA[3] = ffma2(bbA[j], W23.y, tA[3]);
            tB[0] = ffma2(bbB[j], W01.x, tB[0]);  tB[1] = ffma2(bbB[j], W01.y, tB[1]);
            tB[2] = ffma2(bbB[j], W23.x, tB[2]);  tB[3] = ffma2(bbB[j], W23.y, tB[3]);
        }
        ull aiA = bcast2(aA[i]), aiB = bcast2(aB[i]);
#pragma unroll
        for (int k = 0; k < 4; ++k) {
            cA[k] = ffma2(aiA, tA[k], cA[k]);
            cB[k] = ffma2(aiB, tB[k], cB[k]);
        }
    }
    unpack2(cA[0], outA[0], outA[1]);  unpack2(cA[1], outA[2], outA[3]);
    unpack2(cA[2], outA[4], outA[5]);  unpack2(cA[3], outA[6], outA[7]);
    unpack2(cB[0], outB[0], outB[1]);  unpack2(cB[1], outB[2], outB[3]);
    unpack2(cB[2], outB[4], outB[5]);  unpack2(cB[3], outB[6], outB[7]);
}

// 8x8->8, two samples share W (512 floats). out may alias b.
__device__ __forceinline__ void contract888_2(const float* aA, const float* bA,
                                              const float* aB, const float* bB,
                                              const float* __restrict__ w,
                                              float* outA, float* outB) {
    ull cA[4] = {0, 0, 0, 0}, cB[4] = {0, 0, 0, 0};
    ull bbA[8], bbB[8];
#pragma unroll
    for (int j = 0; j < 8; ++j) { bbA[j] = bcast2(bA[j]); bbB[j] = bcast2(bB[j]); }
#pragma unroll
    for (int i = 0; i < 8; ++i) {
        ull tA[4] = {0, 0, 0, 0}, tB[4] = {0, 0, 0, 0};
        const float* base = w + i * 64;
#pragma unroll
        for (int j = 0; j < 8; ++j) {
            const ulonglong2* wp = reinterpret_cast<const ulonglong2*>(base + j * 8);
            ulonglong2 W01 = wp[0];
            ulonglong2 W23 = wp[1];
            tA[0] = ffma2(bbA[j], W01.x, tA[0]);  tA[1] = ffma2(bbA[j], W01.y, tA[1]);
            tA[2] = ffma2(bbA[j], W23.x, tA[2]);  tA[3] = ffma2(bbA[j], W23.y, tA[3]);
            tB[0] = ffma2(bbB[j], W01.x, tB[0]);  tB[1] = ffma2(bbB[j], W01.y, tB[1]);
            tB[2] = ffma2(bbB[j], W23.x, tB[2]);  tB[3] = ffma2(bbB[j], W23.y, tB[3]);
        }
        ull aiA = bcast2(aA[i]), aiB = bcast2(aB[i]);
#pragma unroll
        for (int k = 0; k < 4; ++k) {
            cA[k] = ffma2(aiA, tA[k], cA[k]);
            cB[k] = ffma2(aiB, tB[k], cB[k]);
        }
    }
    unpack2(cA[0], outA[0], outA[1]);  unpack2(cA[1], outA[2], outA[3]);
    unpack2(cA[2], outA[4], outA[5]);  unpack2(cA[3], outA[6], outA[7]);
    unpack2(cB[0], outB[0], outB[1]);  unpack2(cB[1], outB[2], outB[3]);
    unpack2(cB[2], outB[4], outB[5]);  unpack2(cB[3], outB[6], outB[7]);
}

__device__ __forceinline__ void scopy4(float* dst, const float* __restrict__ src, int n4) {
    const float4* s = reinterpret_cast<const float4*>(src);
    float4* d = reinterpret_cast<float4*>(dst);
    for (int i = threadIdx.x; i < n4; i += THREADS) d[i] = s[i];
}

__global__ void __launch_bounds__(THREADS, 2)
tn_half_kernel(const float* __restrict__ x,
               const float* __restrict__ w7, const float* __restrict__ w6,
               const float* __restrict__ w5, const float* __restrict__ w4,
               const float* __restrict__ w3, const float* __restrict__ w2,
               const float* __restrict__ w1) {
    extern __shared__ float sw[];

    const int side = blockIdx.x >> 7;        // 0 = left half, 1 = right half
    const int blk  = blockIdx.x & 127;

    // stage this half's weights
    scopy4(sw + H7, w7 + side * 1024,  1024 / 4);
    scopy4(sw + H6, w6 + side * 4096,  4096 / 4);
    scopy4(sw + H5, w5 + side * 8192,  8192 / 4);
    scopy4(sw + H4, w4 + side * 4096,  4096 / 4);
    scopy4(sw + H3, w3 + side * 2048,  2048 / 4);
    scopy4(sw + H2, w2 + side * 1024,  1024 / 4);
    scopy4(sw + H1, w1 + side * 512,    512 / 4);
    __syncthreads();

    const int bA = blk * THREADS + threadIdx.x;   // sample A
    const int bB = bA + HALF;                     // sample B
    const float4* xA = reinterpret_cast<const float4*>(x) + (size_t)bA * 128 + side * 64;
    const float4* xB = reinterpret_cast<const float4*>(x) + (size_t)bB * 128 + side * 64;

    float stkA0[8], stkA1[8], stkA2[8], stkA3[8], stkA4[8];
    float stkB0[8], stkB1[8], stkB2[8], stkB3[8], stkB4[8];

#pragma unroll 1
    for (int m = 0; m < 32; ++m) {
        float4 qA0 = __ldg(xA + 2 * m);
        float4 qA1 = __ldg(xA + 2 * m + 1);
        float4 qB0 = __ldg(xB + 2 * m);
        float4 qB1 = __ldg(xB + 2 * m + 1);

        float laA[4], lbA[4], laB[4], lbB[4];
        leaf2(qA0, qB0, sw + H7 + (2 * m) * 16, laA, laB);
        leaf2(qA1, qB1, sw + H7 + (2 * m + 1) * 16, lbA, lbB);

        float curA[8], curB[8];
        contract448_2(laA, lbA, laB, lbB, sw + H6 + m * 128, curA, curB);

        if (!(m & 1)) {
            cp8(stkA0, curA);  cp8(stkB0, curB);
        } else {
            contract888_2(stkA0, curA, stkB0, curB, sw + H5 + (m >> 1) * 512, curA, curB);
            if (!((m >> 1) & 1)) {
                cp8(stkA1, curA);  cp8(stkB1, curB);
            } else {
                contract888_2(stkA1, curA, stkB1, curB, sw + H4 + (m >> 2) * 512, curA, curB);
                if (!((m >> 2) & 1)) {
                    cp8(stkA2, curA);  cp8(stkB2, curB);
                } else {
                    contract888_2(stkA2, curA, stkB2, curB, sw + H3 + (m >> 3) * 512, curA, curB);
                    if (!((m >> 3) & 1)) {
                        cp8(stkA3, curA);  cp8(stkB3, curB);
                    } else {
                        contract888_2(stkA3, curA, stkB3, curB, sw + H2 + (m >> 4) * 512, curA, curB);
                        if (!((m >> 4) & 1)) {
                            cp8(stkA4, curA);  cp8(stkB4, curB);
                        } else {
                            // m == 31: final merge of this half-tree
                            contract888_2(stkA4, curA, stkB4, curB, sw + H1, curA, curB);
                            float4* hb = g_hbuf + ((size_t)side * NB) * 2;
                            hb[(size_t)bA * 2 + 0] = make_float4(curA[0], curA[1], curA[2], curA[3]);
                            hb[(size_t)bA * 2 + 1] = make_float4(curA[4], curA[5], curA[6], curA[7]);
                            hb[(size_t)bB * 2 + 0] = make_float4(curB[0], curB[1], curB[2], curB[3]);
                            hb[(size_t)bB * 2 + 1] = make_float4(curB[4], curB[5], curB[6], curB[7]);
                        }
                    }
                }
            }
        }
    }
}

// root: out[b,l] = sum_{i,j<8} hL_i hR_j w0[(i*8+j)*2 + l]
__global__ void __launch_bounds__(THREADS)
tn_root_kernel(const float* __restrict__ w0, float* __restrict__ out) {
    __shared__ float w0s[128];
    if (threadIdx.x < 32) {
        reinterpret_cast<float4*>(w0s)[threadIdx.x] =
            reinterpret_cast<const float4*>(w0)[threadIdx.x];
    }
    __syncthreads();

    const int b = blockIdx.x * THREADS + threadIdx.x;
    float4 l0 = g_hbuf[(size_t)b * 2 + 0];
    float4 l1 = g_hbuf[(size_t)b * 2 + 1];
    float4 r0 = g_hbuf[(size_t)(NB + b) * 2 + 0];
    float4 r1 = g_hbuf[(size_t)(NB + b) * 2 + 1];
    float hL[8] = {l0.x, l0.y, l0.z, l0.w, l1.x, l1.y, l1.z, l1.w};
    float hR[8] = {r0.x, r0.y, r0.z, r0.w, r1.x, r1.y, r1.z, r1.w};

    ull acc = 0ull;
#pragma unroll
    for (int i = 0; i < 8; ++i) {
#pragma unroll
        for (int j = 0; j < 8; ++j) {
            ull W = *reinterpret_cast<const ull*>(w0s + (i * 8 + j) * 2);
            acc = ffma2(bcast2(hL[i] * hR[j]), W, acc);
        }
    }
    float r0f, r1f;
    unpack2(acc, r0f, r1f);
    reinterpret_cast<float2*>(out)[b] = make_float2(r0f, r1f);
}

extern "C" void kernel_launch(void* const* d_in, const int* in_sizes, int n_in,
                              void* d_out, int out_size) {
    const float* x  = (const float*)d_in[0];
    const float* w7 = (const float*)d_in[1];
    const float* w6 = (const float*)d_in[2];
    const float* w5 = (const float*)d_in[3];
    const float* w4 = (const float*)d_in[4];
    const float* w3 = (const float*)d_in[5];
    const float* w2 = (const float*)d_in[6];
    const float* w1 = (const float*)d_in[7];
    const float* w0 = (const float*)d_in[8];
    float* out = (float*)d_out;

    const size_t smem = SMEM_FLOATS * sizeof(float);
    cudaFuncSetAttribute(tn_half_kernel, cudaFuncAttributeMaxDynamicSharedMemorySize, (int)smem);
    tn_half_kernel<<<NBLOCKS, THREADS, smem>>>(x, w7, w6, w5, w4, w3, w2, w1);
    tn_root_kernel<<<NB / THREADS, THREADS>>>(w0, out);
}

// round 4
// speedup vs baseline: 1.1814x; 1.1814x over previous
#include <cuda_runtime.h>

// ---------------------------------------------------------------------------
// TNModel binary-tree TN, B=65536. Round 4: quarter-tree split.
// Kernel 1: each CTA computes one quarter subtree (levels w7..w2, 40 KB
// weights in smem) for 2 samples/thread, 128-thread CTAs, 4 CTAs/SM ->
// 16 warps/SM with natural regs ~<=128 (4-level register stack).
// Kernel 2: merges 4 quarter vectors via w1 (2x 8x8x8) + w0 root.
// ---------------------------------------------------------------------------

#define NB       65536
#define HALF     (NB / 2)            // 32768
#define T1       128                 // threads, kernel 1
#define BLK_Q    256                 // blocks per quarter = HALF / T1
#define NBLOCKS1 (4 * BLK_Q)         // 1024
#define T2       256                 // threads, kernel 2

// quarter-tree shared-memory float offsets
#define Q7 0                      // 32 x 16   =  512
#define Q6 (Q7 + 512)             // 16 x 128  = 2048
#define Q5 (Q6 + 2048)            //  8 x 512  = 4096
#define Q4 (Q5 + 4096)            //  4 x 512  = 2048
#define Q3 (Q4 + 2048)            //  2 x 512  = 1024
#define Q2 (Q3 + 1024)            //  1 x 512  =  512
#define SMEM1_FLOATS (Q2 + 512)   // 10240 floats = 40960 bytes

typedef unsigned long long ull;

__device__ float4 g_qbuf[4 * NB * 2];   // [quarter][sample][2 x float4]

__device__ __forceinline__ ull ffma2(ull a, ull b, ull c) {
    ull d;
    asm("fma.rn.f32x2 %0, %1, %2, %3;" : "=l"(d) : "l"(a), "l"(b), "l"(c));
    return d;
}
__device__ __forceinline__ ull bcast2(float x) {
    ull r;
    asm("mov.b64 %0, {%1, %1};" : "=l"(r) : "f"(x));
    return r;
}
__device__ __forceinline__ void unpack2(ull v, float& lo, float& hi) {
    asm("mov.b64 {%0, %1}, %2;" : "=f"(lo), "=f"(hi) : "l"(v));
}
__device__ __forceinline__ void cp8(float* d, const float* s) {
#pragma unroll
    for (int k = 0; k < 8; ++k) d[k] = s[k];
}

// leaf for two samples sharing W (16 floats): h[k<4] = sum_{i,j<2} e_i o_j w[ijk]
__device__ __forceinline__ void leaf2(float4 qa, float4 qb,
                                      const float* __restrict__ w,
                                      float* hA, float* hB) {
    ull cA0 = 0, cA1 = 0, cB0 = 0, cB1 = 0;
    float eA[2] = {qa.x, qa.y}, oA[2] = {qa.z, qa.w};
    float eB[2] = {qb.x, qb.y}, oB[2] = {qb.z, qb.w};
#pragma unroll
    for (int i = 0; i < 2; ++i) {
#pragma unroll
        for (int j = 0; j < 2; ++j) {
            const ulonglong2 W = *reinterpret_cast<const ulonglong2*>(w + (i * 2 + j) * 4);
            ull pA = bcast2(eA[i] * oA[j]);
            ull pB = bcast2(eB[i] * oB[j]);
            cA0 = ffma2(pA, W.x, cA0);  cA1 = ffma2(pA, W.y, cA1);
            cB0 = ffma2(pB, W.x, cB0);  cB1 = ffma2(pB, W.y, cB1);
        }
    }
    unpack2(cA0, hA[0], hA[1]);  unpack2(cA1, hA[2], hA[3]);
    unpack2(cB0, hB[0], hB[1]);  unpack2(cB1, hB[2], hB[3]);
}

// 4x4->8, two samples sharing W (128 floats). Broadcasts done inline (low reg use).
__device__ __forceinline__ void contract448_2(const float* aA, const float* bA,
                                              const float* aB, const float* bB,
                                              const float* __restrict__ w,
                                              float* outA, float* outB) {
    ull cA[4] = {0, 0, 0, 0}, cB[4] = {0, 0, 0, 0};
#pragma unroll
    for (int i = 0; i < 4; ++i) {
        ull tA[4] = {0, 0, 0, 0}, tB[4] = {0, 0, 0, 0};
#pragma unroll
        for (int j = 0; j < 4; ++j) {
            const ulonglong2* wp = reinterpret_cast<const ulonglong2*>(w + (i * 4 + j) * 8);
            ulonglong2 W01 = wp[0];
            ulonglong2 W23 = wp[1];
            ull bb = bcast2(bA[j]);
            tA[0] = ffma2(bb, W01.x, tA[0]);  tA[1] = ffma2(bb, W01.y, tA[1]);
            tA[2] = ffma2(bb, W23.x, tA[2]);  tA[3] = ffma2(bb, W23.y, tA[3]);
            bb = bcast2(bB[j]);
            tB[0] = ffma2(bb, W01.x, tB[0]);  tB[1] = ffma2(bb, W01.y, tB[1]);
            tB[2] = ffma2(bb, W23.x, tB[2]);  tB[3] = ffma2(bb, W23.y, tB[3]);
        }
        ull ai = bcast2(aA[i]);
        cA[0] = ffma2(ai, tA[0], cA[0]);  cA[1] = ffma2(ai, tA[1], cA[1]);
        cA[2] = ffma2(ai, tA[2], cA[2]);  cA[3] = ffma2(ai, tA[3], cA[3]);
        ai = bcast2(aB[i]);
        cB[0] = ffma2(ai, tB[0], cB[0]);  cB[1] = ffma2(ai, tB[1], cB[1]);
        cB[2] = ffma2(ai, tB[2], cB[2]);  cB[3] = ffma2(ai, tB[3], cB[3]);
    }
    unpack2(cA[0], outA[0], outA[1]);  unpack2(cA[1], outA[2], outA[3]);
    unpack2(cA[2], outA[4], outA[5]);  unpack2(cA[3], outA[6], outA[7]);
    unpack2(cB[0], outB[0], outB[1]);  unpack2(cB[1], outB[2], outB[3]);
    unpack2(cB[2], outB[4], outB[5]);  unpack2(cB[3], outB[6], outB[7]);
}

// 8x8->8, two samples sharing W (512 floats). out may alias b.
__device__ __forceinline__ void contract888_2(const float* aA, const float* bA,
                                              const float* aB, const float* bB,
                                              const float* __restrict__ w,
                                              float* outA, float* outB) {
    ull cA[4] = {0, 0, 0, 0}, cB[4] = {0, 0, 0, 0};
#pragma unroll
    for (int i = 0; i < 8; ++i) {
        ull tA[4] = {0, 0, 0, 0}, tB[4] = {0, 0, 0, 0};
        const float* base = w + i * 64;
#pragma unroll
        for (int j = 0; j < 8; ++j) {
            const ulonglong2* wp = reinterpret_cast<const ulonglong2*>(base + j * 8);
            ulonglong2 W01 = wp[0];
            ulonglong2 W23 = wp[1];
            ull bb = bcast2(bA[j]);
            tA[0] = ffma2(bb, W01.x, tA[0]);  tA[1] = ffma2(bb, W01.y, tA[1]);
            tA[2] = ffma2(bb, W23.x, tA[2]);  tA[3] = ffma2(bb, W23.y, tA[3]);
            bb = bcast2(bB[j]);
            tB[0] = ffma2(bb, W01.x, tB[0]);  tB[1] = ffma2(bb, W01.y, tB[1]);
            tB[2] = ffma2(bb, W23.x, tB[2]);  tB[3] = ffma2(bb, W23.y, tB[3]);
        }
        ull ai = bcast2(aA[i]);
        cA[0] = ffma2(ai, tA[0], cA[0]);  cA[1] = ffma2(ai, tA[1], cA[1]);
        cA[2] = ffma2(ai, tA[2], cA[2]);  cA[3] = ffma2(ai, tA[3], cA[3]);
        ai = bcast2(aB[i]);
        cB[0] = ffma2(ai, tB[0], cB[0]);  cB[1] = ffma2(ai, tB[1], cB[1]);
        cB[2] = ffma2(ai, tB[2], cB[2]);  cB[3] = ffma2(ai, tB[3], cB[3]);
    }
    unpack2(cA[0], outA[0], outA[1]);  unpack2(cA[1], outA[2], outA[3]);
    unpack2(cA[2], outA[4], outA[5]);  unpack2(cA[3], outA[6], outA[7]);
    unpack2(cB[0], outB[0], outB[1]);  unpack2(cB[1], outB[2], outB[3]);
    unpack2(cB[2], outB[4], outB[5]);  unpack2(cB[3], outB[6], outB[7]);
}

// 8x8->8 single sample
__device__ __forceinline__ void contract888_1(const float* a, const float* b,
                                              const float* __restrict__ w, float* out) {
    ull c[4] = {0, 0, 0, 0};
#pragma unroll
    for (int i = 0; i < 8; ++i) {
        ull t[4] = {0, 0, 0, 0};
        const float* base = w + i * 64;
#pragma unroll
        for (int j = 0; j < 8; ++j) {
            const ulonglong2* wp = reinterpret_cast<const ulonglong2*>(base + j * 8);
            ulonglong2 W01 = wp[0];
            ulonglong2 W23 = wp[1];
            ull bb = bcast2(b[j]);
            t[0] = ffma2(bb, W01.x, t[0]);  t[1] = ffma2(bb, W01.y, t[1]);
            t[2] = ffma2(bb, W23.x, t[2]);  t[3] = ffma2(bb, W23.y, t[3]);
        }
        ull ai = bcast2(a[i]);
        c[0] = ffma2(ai, t[0], c[0]);  c[1] = ffma2(ai, t[1], c[1]);
        c[2] = ffma2(ai, t[2], c[2]);  c[3] = ffma2(ai, t[3], c[3]);
    }
    unpack2(c[0], out[0], out[1]);  unpack2(c[1], out[2], out[3]);
    unpack2(c[2], out[4], out[5]);  unpack2(c[3], out[6], out[7]);
}

__device__ __forceinline__ void scopy4(float* dst, const float* __restrict__ src, int n4) {
    const float4* s = reinterpret_cast<const float4*>(src);
    float4* d = reinterpret_cast<float4*>(dst);
    for (int i = threadIdx.x; i < n4; i += blockDim.x) d[i] = s[i];
}

__global__ void __launch_bounds__(T1, 4)
tn_quarter_kernel(const float* __restrict__ x,
                  const float* __restrict__ w7, const float* __restrict__ w6,
                  const float* __restrict__ w5, const float* __restrict__ w4,
                  const float* __restrict__ w3, const float* __restrict__ w2) {
    extern __shared__ float sw[];

    const int q   = blockIdx.x >> 8;      // quarter 0..3
    const int blk = blockIdx.x & 255;

    // stage this quarter's weights
    scopy4(sw + Q7, w7 + q * 512,   512 / 4);
    scopy4(sw + Q6, w6 + q * 2048, 2048 / 4);
    scopy4(sw + Q5, w5 + q * 4096, 4096 / 4);
    scopy4(sw + Q4, w4 + q * 2048, 2048 / 4);
    scopy4(sw + Q3, w3 + q * 1024, 1024 / 4);
    scopy4(sw + Q2, w2 + q * 512,   512 / 4);
    __syncthreads();

    const int bA = blk * T1 + threadIdx.x;     // sample A
    const int bB = bA + HALF;                  // sample B
    const float4* xA = reinterpret_cast<const float4*>(x) + (size_t)bA * 128 + q * 32;
    const float4* xB = reinterpret_cast<const float4*>(x) + (size_t)bB * 128 + q * 32;

    float stkA0[8], stkA1[8], stkA2[8], stkA3[8];
    float stkB0[8], stkB1[8], stkB2[8], stkB3[8];

#pragma unroll 1
    for (int m = 0; m < 16; ++m) {
        float4 qA0 = __ldg(xA + 2 * m);
        float4 qA1 = __ldg(xA + 2 * m + 1);
        float4 qB0 = __ldg(xB + 2 * m);
        float4 qB1 = __ldg(xB + 2 * m + 1);

        float laA[4], lbA[4], laB[4], lbB[4];
        leaf2(qA0, qB0, sw + Q7 + (2 * m) * 16, laA, laB);
        leaf2(qA1, qB1, sw + Q7 + (2 * m + 1) * 16, lbA, lbB);

        float curA[8], curB[8];
        contract448_2(laA, lbA, laB, lbB, sw + Q6 + m * 128, curA, curB);

        if (!(m & 1)) {
            cp8(stkA0, curA);  cp8(stkB0, curB);
        } else {
            contract888_2(stkA0, curA, stkB0, curB, sw + Q5 + (m >> 1) * 512, curA, curB);
            if (!((m >> 1) & 1)) {
                cp8(stkA1, curA);  cp8(stkB1, curB);
            } else {
                contract888_2(stkA1, curA, stkB1, curB, sw + Q4 + (m >> 2) * 512, curA, curB);
                if (!((m >> 2) & 1)) {
                    cp8(stkA2, curA);  cp8(stkB2, curB);
                } else {
                    contract888_2(stkA2, curA, stkB2, curB, sw + Q3 + (m >> 3) * 512, curA, curB);
                    if (!((m >> 3) & 1)) {
                        cp8(stkA3, curA);  cp8(stkB3, curB);
                    } else {
                        // m == 15: final merge of this quarter (w2 node)
                        contract888_2(stkA3, curA, stkB3, curB, sw + Q2, curA, curB);
                        float4* qb = g_qbuf + ((size_t)q * NB) * 2;
                        qb[(size_t)bA * 2 + 0] = make_float4(curA[0], curA[1], curA[2], curA[3]);
                        qb[(size_t)bA * 2 + 1] = make_float4(curA[4], curA[5], curA[6], curA[7]);
                        qb[(size_t)bB * 2 + 0] = make_float4(curB[0], curB[1], curB[2], curB[3]);
                        qb[(size_t)bB * 2 + 1] = make_float4(curB[4], curB[5], curB[6], curB[7]);
                    }
                }
            }
        }
    }
}

// merge: hL = 888(q0,q1,w1[0]); hR = 888(q2,q3,w1[1]); out = root(hL,hR,w0)
__global__ void __launch_bounds__(T2)
tn_merge_kernel(const float* __restrict__ w1, const float* __restrict__ w0,
                float* __restrict__ out) {
    __shared__ float w1s[1024];
    __shared__ float w0s[128];
    scopy4(w1s, w1, 1024 / 4);
    scopy4(w0s, w0, 128 / 4);
    __syncthreads();

    const int b = blockIdx.x * T2 + threadIdx.x;

    float v[4][8];
#pragma unroll
    for (int qq = 0; qq < 4; ++qq) {
        float4 p0 = g_qbuf[((size_t)qq * NB + b) * 2 + 0];
        float4 p1 = g_qbuf[((size_t)qq * NB + b) * 2 + 1];
        v[qq][0] = p0.x; v[qq][1] = p0.y; v[qq][2] = p0.z; v[qq][3] = p0.w;
        v[qq][4] = p1.x; v[qq][5] = p1.y; v[qq][6] = p1.z; v[qq][7] = p1.w;
    }

    float hL[8], hR[8];
    contract888_1(v[0], v[1], w1s, hL);
    contract888_1(v[2], v[3], w1s + 512, hR);

    ull acc = 0ull;
#pragma unroll
    for (int i = 0; i < 8; ++i) {
        ull ai = bcast2(hL[i]);
#pragma unroll
        for (int j = 0; j < 8; ++j) {
            ull W = *reinterpret_cast<const ull*>(w0s + (i * 8 + j) * 2);
            acc = ffma2(ffma2(ai, bcast2(hR[j]), 0ull), W, acc);
        }
    }
    float r0, r1;
    unpack2(acc, r0, r1);
    reinterpret_cast<float2*>(out)[b] = make_float2(r0, r1);
}

extern "C" void kernel_launch(void* const* d_in, const int* in_sizes, int n_in,
                              void* d_out, int out_size) {
    const float* x  = (const float*)d_in[0];
    const float* w7 = (const float*)d_in[1];
    const float* w6 = (const float*)d_in[2];
    const float* w5 = (const float*)d_in[3];
    const float* w4 = (const float*)d_in[4];
    const float* w3 = (const float*)d_in[5];
    const float* w2 = (const float*)d_in[6];
    const float* w1 = (const float*)d_in[7];
    const float* w0 = (const float*)d_in[8];
    float* out = (float*)d_out;

    const size_t smem = SMEM1_FLOATS * sizeof(float);
    cudaFuncSetAttribute(tn_quarter_kernel, cudaFuncAttributeMaxDynamicSharedMemorySize, (int)smem);
    tn_quarter_kernel<<<NBLOCKS1, T1, smem>>>(x, w7, w6, w5, w4, w3, w2);
    tn_merge_kernel<<<NB / T2, T2>>>(w1, w0, out);
}